// round 2
// baseline (speedup 1.0000x reference)
#include <cuda_runtime.h>
#include <math.h>

#define BB 2
#define NN 4096
#define KK 30
#define RPB 8           // rows per block in knn kernel
#define TPB 256
#define NBINS 512
#define CAP 256

#define SZ_POS (BB*NN*KK*16)
#define SZ_AD  (BB*NN*3)
#define SZ_OF  (BB*NN*KK*3)
#define SZ_GS  (BB*NN*KK*15)
#define SZ_DN  (BB*NN*KK)

#define OFF_POS 0
#define OFF_AD  (OFF_POS + SZ_POS)
#define OFF_OF  (OFF_AD  + SZ_AD)
#define OFF_GS  (OFF_OF  + SZ_OF)
#define OFF_DN  (OFF_GS  + SZ_GS)
#define OFF_EI  (OFF_DN  + SZ_DN)

// ---- scratch (no allocations allowed) ----
static __device__ int   g_eidx[BB*NN*KK];
static __device__ float g_Omat[BB*NN*9];
static __device__ float g_freq[8];
static __device__ float g_mu[15];

// ---- exact-rounding helpers (block FMA contraction / fast-math) ----
__device__ __forceinline__ float fadd_(float a, float b){ return __fadd_rn(a,b); }
__device__ __forceinline__ float fsub_(float a, float b){ return __fsub_rn(a,b); }
__device__ __forceinline__ float fmul_(float a, float b){ return __fmul_rn(a,b); }
__device__ __forceinline__ float dot3_(float ax,float ay,float az,
                                       float bx,float by,float bz){
    return fadd_(fadd_(fmul_(ax,bx), fmul_(ay,by)), fmul_(az,bz));
}
__device__ __forceinline__ void norm3_(float &x, float &y, float &z){
    float n = __fsqrt_rn(dot3_(x,y,z,x,y,z));
    n = fmaxf(n, 1e-12f);
    x = __fdiv_rn(x,n); y = __fdiv_rn(y,n); z = __fdiv_rn(z,n);
}
__device__ __forceinline__ void cross3_(float ax,float ay,float az,
                                        float bx,float by,float bz,
                                        float &cx,float &cy,float &cz){
    cx = fsub_(fmul_(ay,bz), fmul_(az,by));
    cy = fsub_(fmul_(az,bx), fmul_(ax,bz));
    cz = fsub_(fmul_(ax,by), fmul_(ay,bx));
}
// squared distance with reference op order: (dx^2 + dy^2) + dz^2
__device__ __forceinline__ float d2_exact(float xi,float yi,float zi,
                                          float xj,float yj,float zj){
    float dx = fsub_(xj,xi), dy = fsub_(yj,yi), dz = fsub_(zj,zi);
    return fadd_(fadd_(fmul_(dx,dx), fmul_(dy,dy)), fmul_(dz,dz));
}
// accurate cos/sin for large args (double range reduction; safe under fast-math)
__device__ __forceinline__ float pcos_(float x){
    double xd = (double)x;
    double k  = rint(xd * 0.15915494309189535);
    double r  = xd - k * 6.283185307179586;
    return cosf((float)r);
}
__device__ __forceinline__ float psin_(float x){
    double xd = (double)x;
    double k  = rint(xd * 0.15915494309189535);
    double r  = xd - k * 6.283185307179586;
    return sinf((float)r);
}

// ---- constants setup (f64 exp of the f32-rounded args the reference uses) ----
__global__ void init_consts_kernel(){
    int t = threadIdx.x;
    if (t < 8){
        float argf = __fmul_rn((float)(2*t), -0.5756462732485115f); // -ln(1e4)/16
        g_freq[t] = (float)exp((double)argf);
    }
    if (t < 15){
        g_mu[t] = (float)((double)t * (20.0/14.0));  // linspace(0,20,15)
    }
}

// ============================================================================
// Kernel A: exact top-30 nearest neighbors per row (histogram radix select)
// ============================================================================
__global__ __launch_bounds__(TPB) void knn_kernel(
    const float* __restrict__ X, float* __restrict__ outD, float* __restrict__ outE)
{
    __shared__ unsigned int hist[RPB][NBINS];
    __shared__ float cval[RPB][CAP];
    __shared__ int   cidx[RPB][CAP];
    __shared__ int   ccnt[RPB];
    __shared__ int   cthr[RPB];
    __shared__ float sXi[RPB][3];

    const int blk = blockIdx.x;
    const int b   = blk / (NN/RPB);
    const int i0  = (blk % (NN/RPB)) * RPB;
    const int t   = threadIdx.x;

    for (int idx = t; idx < RPB*NBINS; idx += TPB)
        ((unsigned int*)hist)[idx] = 0u;
    if (t < RPB) ccnt[t] = 0;
    if (t < RPB*3) ((float*)sXi)[t] = X[(b*NN + i0)*3 + t];
    __syncthreads();

    float xi[RPB], yi[RPB], zi[RPB];
    #pragma unroll
    for (int r = 0; r < RPB; r++){ xi[r]=sXi[r][0]; yi[r]=sXi[r][1]; zi[r]=sXi[r][2]; }

    const float* Xb = X + b*NN*3;

    // ---- pass 1: d^2 histogram (512 bins = exponent*8 + 3 mantissa bits) ----
    for (int m = 0; m < NN/TPB; m++){
        int j = m*TPB + t;
        float xj = __ldg(&Xb[j*3+0]);
        float yj = __ldg(&Xb[j*3+1]);
        float zj = __ldg(&Xb[j*3+2]);
        #pragma unroll
        for (int r = 0; r < RPB; r++){
            float d2 = d2_exact(xi[r],yi[r],zi[r],xj,yj,zj);
            int key = (int)(__float_as_uint(d2) >> 20) - 832;
            key = max(0, min(NBINS-1, key));
            atomicAdd(&hist[r][key], 1u);
        }
    }
    __syncthreads();

    // ---- threshold bin per row (warp w handles row w) ----
    const int wid = t >> 5, lane = t & 31;
    if (wid < RPB){
        unsigned int s = 0;
        #pragma unroll
        for (int q = 0; q < NBINS/32; q++) s += hist[wid][lane*(NBINS/32)+q];
        unsigned int cum = s;
        #pragma unroll
        for (int off = 1; off < 32; off <<= 1){
            unsigned int v = __shfl_up_sync(0xffffffffu, cum, off);
            if (lane >= off) cum += v;
        }
        unsigned int ball = __ballot_sync(0xffffffffu, cum >= (unsigned)KK);
        int first = __ffs(ball) - 1;
        if (lane == first){
            unsigned int c = cum - s;
            int T = first*(NBINS/32);
            for (int q = 0; q < NBINS/32; q++){
                c += hist[wid][first*(NBINS/32)+q];
                if (c >= (unsigned)KK){ T = first*(NBINS/32)+q; break; }
            }
            cthr[wid] = min(T+1, NBINS-1);   // +1 margin bin for safety
        }
    }
    __syncthreads();

    int thr[RPB];
    #pragma unroll
    for (int r = 0; r < RPB; r++) thr[r] = cthr[r];

    // ---- pass 2: compact survivors (store exact reference-order D) ----
    for (int m = 0; m < NN/TPB; m++){
        int j = m*TPB + t;
        float xj = __ldg(&Xb[j*3+0]);
        float yj = __ldg(&Xb[j*3+1]);
        float zj = __ldg(&Xb[j*3+2]);
        #pragma unroll
        for (int r = 0; r < RPB; r++){
            float d2 = d2_exact(xi[r],yi[r],zi[r],xj,yj,zj);
            int key = (int)(__float_as_uint(d2) >> 20) - 832;
            key = max(0, min(NBINS-1, key));
            if (key <= thr[r]){
                int p = atomicAdd(&ccnt[r], 1);
                if (p < CAP){
                    cval[r][p] = __fsqrt_rn(fadd_(d2, 1e-6f));
                    cidx[r][p] = j;
                }
            }
        }
    }
    __syncthreads();

    // ---- 30 sorted extractions per row (warp w = row w; tie-break low idx) ----
    if (wid < RPB){
        int cnt = min(ccnt[wid], CAP);
        float* cv = cval[wid];
        int*   ci = cidx[wid];
        const int base = (b*NN + i0 + wid)*KK;
        const float INF = __int_as_float(0x7f800000);
        for (int k = 0; k < KK; k++){
            float bv = INF; int bi = 0x7fffffff; int bs = -1;
            for (int c = lane; c < cnt; c += 32){
                float v = cv[c]; int id = ci[c];
                if (v < bv || (v == bv && id < bi)){ bv=v; bi=id; bs=c; }
            }
            #pragma unroll
            for (int off = 16; off; off >>= 1){
                float ov = __shfl_down_sync(0xffffffffu, bv, off);
                int   oi = __shfl_down_sync(0xffffffffu, bi, off);
                int   os = __shfl_down_sync(0xffffffffu, bs, off);
                if (ov < bv || (ov == bv && oi < bi)){ bv=ov; bi=oi; bs=os; }
            }
            if (lane == 0){
                outD[base + k]   = bv;
                outE[base + k]   = (float)bi;
                g_eidx[base + k] = bi;
                cv[bs] = INF;               // consume winner
            }
            __syncwarp();
        }
    }
}

// ============================================================================
// Kernel B: per-node orientation matrix O and AD features
// ============================================================================
__global__ void node_kernel(const float* __restrict__ X, float* __restrict__ outAD){
    int id = blockIdx.x*blockDim.x + threadIdx.x;
    if (id >= BB*NN) return;
    int b = id / NN, n = id % NN;

    float O0=0,O1=0,O2=0,O3v=0,O4=0,O5=0,O6=0,O7=0,O8=0;
    float a0=0,a1=0,a2=0;

    if (n >= 1 && n <= NN-3){
        const float* Xb = X + b*NN*3;
        float p0x=Xb[(n-1)*3+0], p0y=Xb[(n-1)*3+1], p0z=Xb[(n-1)*3+2];
        float p1x=Xb[(n  )*3+0], p1y=Xb[(n  )*3+1], p1z=Xb[(n  )*3+2];
        float p2x=Xb[(n+1)*3+0], p2y=Xb[(n+1)*3+1], p2z=Xb[(n+1)*3+2];
        float p3x=Xb[(n+2)*3+0], p3y=Xb[(n+2)*3+1], p3z=Xb[(n+2)*3+2];

        float u2x=fsub_(p1x,p0x), u2y=fsub_(p1y,p0y), u2z=fsub_(p1z,p0z); norm3_(u2x,u2y,u2z);
        float u1x=fsub_(p2x,p1x), u1y=fsub_(p2y,p1y), u1z=fsub_(p2z,p1z); norm3_(u1x,u1y,u1z);
        float u0x=fsub_(p3x,p2x), u0y=fsub_(p3y,p2y), u0z=fsub_(p3z,p2z); norm3_(u0x,u0y,u0z);

        float n2x,n2y,n2z; cross3_(u2x,u2y,u2z,u1x,u1y,u1z,n2x,n2y,n2z); norm3_(n2x,n2y,n2z);
        float n1x,n1y,n1z; cross3_(u1x,u1y,u1z,u0x,u0y,u0z,n1x,n1y,n1z); norm3_(n1x,n1y,n1z);

        const float lo = (float)(-1.0 + 1e-6);
        const float hi = (float)( 1.0 - 1e-6);
        float cosA = fminf(fmaxf(-dot3_(u1x,u1y,u1z,u0x,u0y,u0z), lo), hi);
        float A = acosf(cosA);
        float cosD = fminf(fmaxf(dot3_(n2x,n2y,n2z,n1x,n1y,n1z), lo), hi);
        float s = dot3_(u2x,u2y,u2z,n1x,n1y,n1z);
        float sg = (s > 0.0f) ? 1.0f : ((s < 0.0f) ? -1.0f : 0.0f);
        float Dang = fmul_(sg, acosf(cosD));

        float sA = sinf(A);
        a0 = cosf(A);
        a1 = fmul_(sA, cosf(Dang));
        a2 = fmul_(sA, sinf(Dang));

        float o1x=fsub_(u2x,u1x), o1y=fsub_(u2y,u1y), o1z=fsub_(u2z,u1z); norm3_(o1x,o1y,o1z);
        float cx,cy,cz; cross3_(o1x,o1y,o1z,n2x,n2y,n2z,cx,cy,cz);
        O0=o1x; O1=o1y; O2=o1z; O3v=n2x; O4=n2y; O5=n2z; O6=cx; O7=cy; O8=cz;
    }
    float* Om = g_Omat + id*9;
    Om[0]=O0; Om[1]=O1; Om[2]=O2; Om[3]=O3v; Om[4]=O4; Om[5]=O5; Om[6]=O6; Om[7]=O7; Om[8]=O8;
    outAD[id*3+0]=a0; outAD[id*3+1]=a1; outAD[id*3+2]=a2;
}

// ============================================================================
// Kernel C1: positional encodings (B,N,K,16)
// ============================================================================
__global__ void pos_kernel(float* __restrict__ outP){
    int id = blockIdx.x*blockDim.x + threadIdx.x;
    if (id >= SZ_POS) return;
    int m = id & 15;
    int e = id >> 4;                 // == (b*NN+i)*KK + k
    int i = (e / KK) % NN;
    int j = g_eidx[e];
    float d = fsub_((float)j, (float)i);
    float angle = fmul_(d, g_freq[m & 7]);
    outP[id] = (m < 8) ? pcos_(angle) : psin_(angle);
}

// ============================================================================
// Kernel C2: gaussian smearing of D_neighbors (B,N,K,15)
// ============================================================================
__global__ void gs_kernel(const float* __restrict__ Dn, float* __restrict__ outG){
    int id = blockIdx.x*blockDim.x + threadIdx.x;
    if (id >= SZ_GS) return;
    int m = id % 15;
    int q = id / 15;
    float D  = Dn[q];
    float tt = __fdiv_rn(fsub_(D, g_mu[m]), 1.3333333333333333f);
    outG[id] = expf(-fmul_(tt,tt));
}

// ============================================================================
// Kernel C3: dU = normalize(O @ (X_nb - X_i))   (B,N,K,3)
// ============================================================================
__global__ void du_kernel(const float* __restrict__ X, float* __restrict__ outO){
    int id = blockIdx.x*blockDim.x + threadIdx.x;
    if (id >= BB*NN*KK) return;
    int ni = id / KK;                 // = b*NN + i
    int i  = ni % NN;
    int b  = ni / NN;
    int j  = g_eidx[id];
    const float* Xb = X + b*NN*3;
    float dx = fsub_(Xb[j*3+0], Xb[i*3+0]);
    float dy = fsub_(Xb[j*3+1], Xb[i*3+1]);
    float dz = fsub_(Xb[j*3+2], Xb[i*3+2]);
    const float* Om = g_Omat + ni*9;
    float v0 = dot3_(Om[0],Om[1],Om[2], dx,dy,dz);
    float v1 = dot3_(Om[3],Om[4],Om[5], dx,dy,dz);
    float v2 = dot3_(Om[6],Om[7],Om[8], dx,dy,dz);
    float n = __fsqrt_rn(dot3_(v0,v1,v2,v0,v1,v2));
    n = fmaxf(n, 1e-12f);
    outO[id*3+0] = __fdiv_rn(v0,n);
    outO[id*3+1] = __fdiv_rn(v1,n);
    outO[id*3+2] = __fdiv_rn(v2,n);
}

// ============================================================================
extern "C" void kernel_launch(void* const* d_in, const int* in_sizes, int n_in,
                              void* d_out, int out_size)
{
    const float* X = (const float*)d_in[0];
    float* out = (float*)d_out;

    init_consts_kernel<<<1, 32>>>();
    knn_kernel<<<BB*NN/RPB, TPB>>>(X, out + OFF_DN, out + OFF_EI);
    node_kernel<<<(BB*NN + 255)/256, 256>>>(X, out + OFF_AD);
    pos_kernel<<<(SZ_POS + 255)/256, 256>>>(out + OFF_POS);
    gs_kernel<<<(SZ_GS + 255)/256, 256>>>(out + OFF_DN, out + OFF_GS);
    du_kernel<<<(BB*NN*KK + 255)/256, 256>>>(X, out + OFF_OF);
}

// round 3
// speedup vs baseline: 1.6161x; 1.6161x over previous
#include <cuda_runtime.h>
#include <math.h>

#define BB 2
#define NN 4096
#define KK 30
#define RPB 8           // rows per block in knn kernel
#define TPB 256
#define NBINS 512
#define CAP 256

#define SZ_POS (BB*NN*KK*16)
#define SZ_AD  (BB*NN*3)
#define SZ_OF  (BB*NN*KK*3)
#define SZ_GS  (BB*NN*KK*15)
#define SZ_DN  (BB*NN*KK)

#define OFF_POS 0
#define OFF_AD  (OFF_POS + SZ_POS)
#define OFF_OF  (OFF_AD  + SZ_AD)
#define OFF_GS  (OFF_OF  + SZ_OF)
#define OFF_DN  (OFF_GS  + SZ_GS)
#define OFF_EI  (OFF_DN  + SZ_DN)

// ---- scratch (no allocations allowed) ----
static __device__ int   g_eidx[BB*NN*KK];
static __device__ float g_Omat[BB*NN*9];
static __device__ float g_freq[8];
static __device__ float g_mu[15];

// ---- exact-rounding helpers (block FMA contraction / fast-math) ----
__device__ __forceinline__ float fadd_(float a, float b){ return __fadd_rn(a,b); }
__device__ __forceinline__ float fsub_(float a, float b){ return __fsub_rn(a,b); }
__device__ __forceinline__ float fmul_(float a, float b){ return __fmul_rn(a,b); }
__device__ __forceinline__ float dot3_(float ax,float ay,float az,
                                       float bx,float by,float bz){
    return fadd_(fadd_(fmul_(ax,bx), fmul_(ay,by)), fmul_(az,bz));
}
__device__ __forceinline__ void norm3_(float &x, float &y, float &z){
    float n = __fsqrt_rn(dot3_(x,y,z,x,y,z));
    n = fmaxf(n, 1e-12f);
    x = __fdiv_rn(x,n); y = __fdiv_rn(y,n); z = __fdiv_rn(z,n);
}
__device__ __forceinline__ void cross3_(float ax,float ay,float az,
                                        float bx,float by,float bz,
                                        float &cx,float &cy,float &cz){
    cx = fsub_(fmul_(ay,bz), fmul_(az,by));
    cy = fsub_(fmul_(az,bx), fmul_(ax,bz));
    cz = fsub_(fmul_(ax,by), fmul_(ay,bx));
}
// squared distance with reference op order: (dx^2 + dy^2) + dz^2
__device__ __forceinline__ float d2_exact(float xi,float yi,float zi,
                                          float xj,float yj,float zj){
    float dx = fsub_(xj,xi), dy = fsub_(yj,yi), dz = fsub_(zj,zi);
    return fadd_(fadd_(fmul_(dx,dx), fmul_(dy,dy)), fmul_(dz,dz));
}

// ---- FP32 Cody-Waite 2pi reduction + MUFU sin/cos ----
// |ang| <= ~4100 -> |k| <= 653 (11 bits). Each fmaf term is exactly
// single-rounded; residual abs error ~5e-7, MUFU abs error ~5e-7.
#define INV_2PI  0.15915494309189535f
#define PI2_C1   6.2831855f          // (float)2pi
#define PI2_C2  -1.7484555e-07f      // 2pi - C1
#define PI2_C3  -5.4469782e-15f      // 2pi - C1 - C2
__device__ __forceinline__ void sincos_red_(float ang, float &s, float &c){
    float k = rintf(ang * INV_2PI);
    float r = fmaf(-k, PI2_C1, ang);
    r = fmaf(-k, PI2_C2, r);
    r = fmaf(-k, PI2_C3, r);
    s = __sinf(r);
    c = __cosf(r);
}

// ---- constants setup (f64 exp of the f32-rounded args the reference uses) ----
__global__ void init_consts_kernel(){
    int t = threadIdx.x;
    if (t < 8){
        float argf = __fmul_rn((float)(2*t), -0.5756462732485115f); // -ln(1e4)/16
        g_freq[t] = (float)exp((double)argf);
    }
    if (t < 15){
        g_mu[t] = (float)((double)t * (20.0/14.0));  // linspace(0,20,15)
    }
}

// ============================================================================
// Kernel A: exact top-30 nearest neighbors per row (histogram radix select)
// ============================================================================
__global__ __launch_bounds__(TPB) void knn_kernel(
    const float* __restrict__ X, float* __restrict__ outD, float* __restrict__ outE)
{
    __shared__ unsigned int hist[RPB][NBINS];
    __shared__ float cval[RPB][CAP];
    __shared__ int   cidx[RPB][CAP];
    __shared__ int   ccnt[RPB];
    __shared__ int   cthr[RPB];
    __shared__ float sXi[RPB][3];

    const int blk = blockIdx.x;
    const int b   = blk / (NN/RPB);
    const int i0  = (blk % (NN/RPB)) * RPB;
    const int t   = threadIdx.x;

    for (int idx = t; idx < RPB*NBINS; idx += TPB)
        ((unsigned int*)hist)[idx] = 0u;
    if (t < RPB) ccnt[t] = 0;
    if (t < RPB*3) ((float*)sXi)[t] = X[(b*NN + i0)*3 + t];
    __syncthreads();

    float xi[RPB], yi[RPB], zi[RPB];
    #pragma unroll
    for (int r = 0; r < RPB; r++){ xi[r]=sXi[r][0]; yi[r]=sXi[r][1]; zi[r]=sXi[r][2]; }

    const float* Xb = X + b*NN*3;

    // ---- pass 1: d^2 histogram (512 bins = exponent*8 + 3 mantissa bits) ----
    for (int m = 0; m < NN/TPB; m++){
        int j = m*TPB + t;
        float xj = __ldg(&Xb[j*3+0]);
        float yj = __ldg(&Xb[j*3+1]);
        float zj = __ldg(&Xb[j*3+2]);
        #pragma unroll
        for (int r = 0; r < RPB; r++){
            float d2 = d2_exact(xi[r],yi[r],zi[r],xj,yj,zj);
            int key = (int)(__float_as_uint(d2) >> 20) - 832;
            key = max(0, min(NBINS-1, key));
            atomicAdd(&hist[r][key], 1u);
        }
    }
    __syncthreads();

    // ---- threshold bin per row (warp w handles row w) ----
    const int wid = t >> 5, lane = t & 31;
    if (wid < RPB){
        unsigned int s = 0;
        #pragma unroll
        for (int q = 0; q < NBINS/32; q++) s += hist[wid][lane*(NBINS/32)+q];
        unsigned int cum = s;
        #pragma unroll
        for (int off = 1; off < 32; off <<= 1){
            unsigned int v = __shfl_up_sync(0xffffffffu, cum, off);
            if (lane >= off) cum += v;
        }
        unsigned int ball = __ballot_sync(0xffffffffu, cum >= (unsigned)KK);
        int first = __ffs(ball) - 1;
        if (lane == first){
            unsigned int c = cum - s;
            int T = first*(NBINS/32);
            for (int q = 0; q < NBINS/32; q++){
                c += hist[wid][first*(NBINS/32)+q];
                if (c >= (unsigned)KK){ T = first*(NBINS/32)+q; break; }
            }
            cthr[wid] = min(T+1, NBINS-1);   // +1 margin bin for safety
        }
    }
    __syncthreads();

    int thr[RPB];
    #pragma unroll
    for (int r = 0; r < RPB; r++) thr[r] = cthr[r];

    // ---- pass 2: compact survivors (store exact reference-order D) ----
    for (int m = 0; m < NN/TPB; m++){
        int j = m*TPB + t;
        float xj = __ldg(&Xb[j*3+0]);
        float yj = __ldg(&Xb[j*3+1]);
        float zj = __ldg(&Xb[j*3+2]);
        #pragma unroll
        for (int r = 0; r < RPB; r++){
            float d2 = d2_exact(xi[r],yi[r],zi[r],xj,yj,zj);
            int key = (int)(__float_as_uint(d2) >> 20) - 832;
            key = max(0, min(NBINS-1, key));
            if (key <= thr[r]){
                int p = atomicAdd(&ccnt[r], 1);
                if (p < CAP){
                    cval[r][p] = __fsqrt_rn(fadd_(d2, 1e-6f));
                    cidx[r][p] = j;
                }
            }
        }
    }
    __syncthreads();

    // ---- 30 sorted extractions per row (warp w = row w; tie-break low idx) ----
    if (wid < RPB){
        int cnt = min(ccnt[wid], CAP);
        float* cv = cval[wid];
        int*   ci = cidx[wid];
        const int base = (b*NN + i0 + wid)*KK;
        const float INF = __int_as_float(0x7f800000);
        for (int k = 0; k < KK; k++){
            float bv = INF; int bi = 0x7fffffff; int bs = -1;
            for (int c = lane; c < cnt; c += 32){
                float v = cv[c]; int id = ci[c];
                if (v < bv || (v == bv && id < bi)){ bv=v; bi=id; bs=c; }
            }
            #pragma unroll
            for (int off = 16; off; off >>= 1){
                float ov = __shfl_down_sync(0xffffffffu, bv, off);
                int   oi = __shfl_down_sync(0xffffffffu, bi, off);
                int   os = __shfl_down_sync(0xffffffffu, bs, off);
                if (ov < bv || (ov == bv && oi < bi)){ bv=ov; bi=oi; bs=os; }
            }
            if (lane == 0){
                outD[base + k]   = bv;
                outE[base + k]   = (float)bi;
                g_eidx[base + k] = bi;
                cv[bs] = INF;               // consume winner
            }
            __syncwarp();
        }
    }
}

// ============================================================================
// Kernel B: per-node orientation matrix O and AD features
// ============================================================================
__global__ void node_kernel(const float* __restrict__ X, float* __restrict__ outAD){
    int id = blockIdx.x*blockDim.x + threadIdx.x;
    if (id >= BB*NN) return;
    int b = id / NN, n = id % NN;

    float O0=0,O1=0,O2=0,O3v=0,O4=0,O5=0,O6=0,O7=0,O8=0;
    float a0=0,a1=0,a2=0;

    if (n >= 1 && n <= NN-3){
        const float* Xb = X + b*NN*3;
        float p0x=Xb[(n-1)*3+0], p0y=Xb[(n-1)*3+1], p0z=Xb[(n-1)*3+2];
        float p1x=Xb[(n  )*3+0], p1y=Xb[(n  )*3+1], p1z=Xb[(n  )*3+2];
        float p2x=Xb[(n+1)*3+0], p2y=Xb[(n+1)*3+1], p2z=Xb[(n+1)*3+2];
        float p3x=Xb[(n+2)*3+0], p3y=Xb[(n+2)*3+1], p3z=Xb[(n+2)*3+2];

        float u2x=fsub_(p1x,p0x), u2y=fsub_(p1y,p0y), u2z=fsub_(p1z,p0z); norm3_(u2x,u2y,u2z);
        float u1x=fsub_(p2x,p1x), u1y=fsub_(p2y,p1y), u1z=fsub_(p2z,p1z); norm3_(u1x,u1y,u1z);
        float u0x=fsub_(p3x,p2x), u0y=fsub_(p3y,p2y), u0z=fsub_(p3z,p2z); norm3_(u0x,u0y,u0z);

        float n2x,n2y,n2z; cross3_(u2x,u2y,u2z,u1x,u1y,u1z,n2x,n2y,n2z); norm3_(n2x,n2y,n2z);
        float n1x,n1y,n1z; cross3_(u1x,u1y,u1z,u0x,u0y,u0z,n1x,n1y,n1z); norm3_(n1x,n1y,n1z);

        const float lo = (float)(-1.0 + 1e-6);
        const float hi = (float)( 1.0 - 1e-6);
        float cosA = fminf(fmaxf(-dot3_(u1x,u1y,u1z,u0x,u0y,u0z), lo), hi);
        float A = acosf(cosA);
        float cosD = fminf(fmaxf(dot3_(n2x,n2y,n2z,n1x,n1y,n1z), lo), hi);
        float s = dot3_(u2x,u2y,u2z,n1x,n1y,n1z);
        float sg = (s > 0.0f) ? 1.0f : ((s < 0.0f) ? -1.0f : 0.0f);
        float Dang = fmul_(sg, acosf(cosD));

        float sA = sinf(A);
        a0 = cosf(A);
        a1 = fmul_(sA, cosf(Dang));
        a2 = fmul_(sA, sinf(Dang));

        float o1x=fsub_(u2x,u1x), o1y=fsub_(u2y,u1y), o1z=fsub_(u2z,u1z); norm3_(o1x,o1y,o1z);
        float cx,cy,cz; cross3_(o1x,o1y,o1z,n2x,n2y,n2z,cx,cy,cz);
        O0=o1x; O1=o1y; O2=o1z; O3v=n2x; O4=n2y; O5=n2z; O6=cx; O7=cy; O8=cz;
    }
    float* Om = g_Omat + id*9;
    Om[0]=O0; Om[1]=O1; Om[2]=O2; Om[3]=O3v; Om[4]=O4; Om[5]=O5; Om[6]=O6; Om[7]=O7; Om[8]=O8;
    outAD[id*3+0]=a0; outAD[id*3+1]=a1; outAD[id*3+2]=a2;
}

// ============================================================================
// Kernel C1: positional encodings — one thread per edge, 16 outputs
// ============================================================================
__global__ __launch_bounds__(256) void pos_kernel(float* __restrict__ outP){
    int e = blockIdx.x*blockDim.x + threadIdx.x;
    if (e >= BB*NN*KK) return;
    int i = (e / KK) % NN;
    int j = g_eidx[e];
    float d = fsub_((float)j, (float)i);

    float co[8], si[8];
    #pragma unroll
    for (int m = 0; m < 8; m++){
        float ang = fmul_(d, g_freq[m]);
        sincos_red_(ang, si[m], co[m]);
    }
    float4* o = (float4*)(outP + (size_t)e*16);
    o[0] = make_float4(co[0],co[1],co[2],co[3]);
    o[1] = make_float4(co[4],co[5],co[6],co[7]);
    o[2] = make_float4(si[0],si[1],si[2],si[3]);
    o[3] = make_float4(si[4],si[5],si[6],si[7]);
}

// ============================================================================
// Kernel C2: gaussian smearing of D_neighbors (B,N,K,15)
// ============================================================================
#define LOG2E 1.4426950408889634f
__global__ void gs_kernel(const float* __restrict__ Dn, float* __restrict__ outG){
    int id = blockIdx.x*blockDim.x + threadIdx.x;
    if (id >= SZ_GS) return;
    int m = id % 15;
    int q = id / 15;
    float D  = __ldg(&Dn[q]);
    float tt = __fdiv_rn(fsub_(D, g_mu[m]), 1.3333333333333333f);
    outG[id] = exp2f(-fmul_(tt,tt) * LOG2E);
}

// ============================================================================
// Kernel C3: dU = normalize(O @ (X_nb - X_i))   (B,N,K,3)
// ============================================================================
__global__ void du_kernel(const float* __restrict__ X, float* __restrict__ outO){
    int id = blockIdx.x*blockDim.x + threadIdx.x;
    if (id >= BB*NN*KK) return;
    int ni = id / KK;                 // = b*NN + i
    int i  = ni % NN;
    int b  = ni / NN;
    int j  = g_eidx[id];
    const float* Xb = X + b*NN*3;
    float dx = fsub_(Xb[j*3+0], Xb[i*3+0]);
    float dy = fsub_(Xb[j*3+1], Xb[i*3+1]);
    float dz = fsub_(Xb[j*3+2], Xb[i*3+2]);
    const float* Om = g_Omat + ni*9;
    float v0 = dot3_(Om[0],Om[1],Om[2], dx,dy,dz);
    float v1 = dot3_(Om[3],Om[4],Om[5], dx,dy,dz);
    float v2 = dot3_(Om[6],Om[7],Om[8], dx,dy,dz);
    float n = __fsqrt_rn(dot3_(v0,v1,v2,v0,v1,v2));
    n = fmaxf(n, 1e-12f);
    outO[id*3+0] = __fdiv_rn(v0,n);
    outO[id*3+1] = __fdiv_rn(v1,n);
    outO[id*3+2] = __fdiv_rn(v2,n);
}

// ============================================================================
extern "C" void kernel_launch(void* const* d_in, const int* in_sizes, int n_in,
                              void* d_out, int out_size)
{
    const float* X = (const float*)d_in[0];
    float* out = (float*)d_out;

    init_consts_kernel<<<1, 32>>>();
    knn_kernel<<<BB*NN/RPB, TPB>>>(X, out + OFF_DN, out + OFF_EI);
    node_kernel<<<(BB*NN + 255)/256, 256>>>(X, out + OFF_AD);
    pos_kernel<<<(BB*NN*KK + 255)/256, 256>>>(out + OFF_POS);
    gs_kernel<<<(SZ_GS + 255)/256, 256>>>(out + OFF_DN, out + OFF_GS);
    du_kernel<<<(BB*NN*KK + 255)/256, 256>>>(X, out + OFF_OF);
}